// round 4
// baseline (speedup 1.0000x reference)
#include <cuda_runtime.h>

// LengthRegulator: out[b,t,:] = x[b, tok(b,t), :] where tok is searchsorted(cumsum(dur), t, 'right')
// Static shapes: B=16, L=512, D=512, T_MAX=4096. Output fp32 [B, T, D].

constexpr int B = 16;
constexpr int L = 512;
constexpr int D = 512;          // 512 floats = 128 float4 per row
constexpr int T = 4096;
constexpr int D4 = D / 4;       // 128

// Scratch token indices: tok[b*T + t], -1 => zero-pad frame. 256 KB device global (no alloc).
__device__ int g_tok[B * T];

// Kernel A: per-batch inclusive scan of durations + binary search per output frame.
// grid = B blocks, 512 threads.
__global__ void scan_search_kernel(const int* __restrict__ dur) {
    __shared__ int s[L];
    const int b = blockIdx.x;
    const int tid = threadIdx.x;

    s[tid] = dur[b * L + tid];
    __syncthreads();

    // Hillis-Steele inclusive scan over 512 elements
    #pragma unroll
    for (int off = 1; off < L; off <<= 1) {
        int v = (tid >= off) ? s[tid - off] : 0;
        __syncthreads();
        s[tid] += v;
        __syncthreads();
    }
    const int total = s[L - 1];

    // Each thread resolves T/512 = 8 frames via upper_bound binary search in SMEM.
    // (Full convergence: loop until lo == hi. 512-wide range needs up to 10 steps,
    //  not 9 — the previous fixed-9 version left a size-1 interval unresolved.)
    #pragma unroll
    for (int t = tid; t < T; t += L) {
        int tok;
        if (t >= total) {
            tok = -1;
        } else {
            int lo = 0, hi = L;
            while (lo < hi) {
                int mid = (lo + hi) >> 1;
                if (s[mid] <= t) lo = mid + 1; else hi = mid;
            }
            tok = lo < (L - 1) ? lo : (L - 1);
        }
        g_tok[b * T + t] = tok;
    }
}

// Kernel B: flat float4 gather/zero-fill. One float4 per thread.
// idx layout: frame = idx >> 7 (b*T + t), lane-within-row c = idx & 127.
__global__ void gather_kernel(const float4* __restrict__ x4, float4* __restrict__ out4) {
    const int idx = blockIdx.x * blockDim.x + threadIdx.x;
    const int fr = idx >> 7;          // b*T + t
    const int c  = idx & (D4 - 1);
    const int b  = fr >> 12;          // / T

    const int tok = g_tok[fr];
    float4 v = make_float4(0.f, 0.f, 0.f, 0.f);
    if (tok >= 0) {
        v = __ldg(&x4[(b * L + tok) * D4 + c]);
    }
    out4[idx] = v;
}

extern "C" void kernel_launch(void* const* d_in, const int* in_sizes, int n_in,
                              void* d_out, int out_size) {
    const float* x   = (const float*)d_in[0];
    const int*   dur = (const int*)d_in[1];
    // d_in[2] = mel_max_length (static 4096, baked into constants)

    scan_search_kernel<<<B, L>>>(dur);

    const int total4 = B * T * D4;          // 8,388,608 float4
    const int threads = 256;
    gather_kernel<<<total4 / threads, threads>>>((const float4*)x, (float4*)d_out);

    (void)in_sizes; (void)n_in; (void)out_size;
}